// round 13
// baseline (speedup 1.0000x reference)
#include <cuda_runtime.h>
#include <math.h>

#define MDIM 4096
#define NT 32             // 32 tile-rows of 128
#define TILE 128
#define NCHUNK 272        // sum over ti of ceil((32-ti)/2)
#define B1f 0.9f
#define B2f 0.999f
#define EPSV 1e-8f
#define LRV 0.1f
#define NSTEPS 199
#define INV254 (1.0f / 254.0f)

// ---- scratch (__device__ globals; no allocation) ----
__device__ float d_Qs[(size_t)MDIM * MDIM];        // fp32 staging (prep only)
__device__ short d_Q16[(size_t)MDIM * MDIM];       // 32 MB main quantized
__device__ signed char d_Q8[(size_t)MDIM * MDIM];  // 16 MB residual
__device__ float d_s1[MDIM];                       // per-row scale
__device__ float d_g[(NSTEPS + 1)][MDIM];
__device__ float d_W[2][MDIM];
__device__ float d_MT[2][MDIM];
__device__ float d_VT[2][MDIM];

// ---------------------------------------------------------------------------
__global__ void prep_qs_kernel(const float* __restrict__ va) {
    __shared__ float tile[32][33];
    int bx = blockIdx.x * 32, by = blockIdx.y * 32;
    if (bx + 32 <= by) return;                   // upper-triangle blocks only
    int tx = threadIdx.x, ty = threadIdx.y;
    tile[ty][tx] = va[(size_t)(bx + ty) * MDIM + (by + tx)];
    __syncthreads();
    size_t idx = (size_t)(by + ty) * MDIM + (bx + tx);
    d_Qs[idx] = 0.5f * (va[idx] + tile[tx][ty]);
}

// ---------------------------------------------------------------------------
// Per-row scale from max|Q[i][j]|, j in [i, 4096) (only used elements).
// ---------------------------------------------------------------------------
__global__ void rowscale_kernel() {
    __shared__ float red[128];
    int i = blockIdx.x;
    int tid = threadIdx.x;
    float m = 0.0f;
    for (int j = i + tid; j < MDIM; j += 128)
        m = fmaxf(m, fabsf(d_Qs[(size_t)i * MDIM + j]));
    red[tid] = m;
    __syncthreads();
    for (int off = 64; off > 0; off >>= 1) {
        if (tid < off) red[tid] = fmaxf(red[tid], red[tid + off]);
        __syncthreads();
    }
    if (tid == 0) d_s1[i] = fmaxf(red[0], 1e-37f) / 32760.0f;
}

// ---------------------------------------------------------------------------
// Quantize upper tiles: q16 = rint(Q/s1), q8 = rint((Q/s1 - q16)*254).
// ---------------------------------------------------------------------------
__global__ void quant_kernel() {
    __shared__ float sinv[TILE];
    int ti = blockIdx.y, tj = blockIdx.x;
    if (tj < ti) return;
    int br = ti * TILE, bc = tj * TILE;
    int tid = threadIdx.x;
    if (tid < TILE) sinv[tid] = 1.0f / d_s1[br + tid];
    __syncthreads();
    for (int idx = tid; idx < TILE * TILE; idx += 256) {
        int r = idx >> 7, c = idx & 127;
        size_t gi = (size_t)(br + r) * MDIM + (bc + c);
        float v = d_Qs[gi] * sinv[r];
        v = fminf(fmaxf(v, -32760.0f), 32760.0f);   // NaN-safe clamp
        float q16f = rintf(v);
        float q8f  = rintf((v - q16f) * 254.0f);
        q8f = fminf(fmaxf(q8f, -127.0f), 127.0f);
        d_Q16[gi] = (short)q16f;
        d_Q8[gi]  = (signed char)q8f;
    }
}

// ---------------------------------------------------------------------------
__global__ void init_kernel() {
    int i = blockIdx.x * blockDim.x + threadIdx.x;
    if (i < MDIM) {
        d_W[0][i] = 1.0f;  d_W[1][i] = 1.0f;
        d_MT[0][i] = 0.0f; d_MT[1][i] = 0.0f;
        d_VT[0][i] = 0.0f; d_VT[1][i] = 0.0f;
    }
    int total = (NSTEPS + 1) * MDIM;
    for (int j = i; j < total; j += gridDim.x * blockDim.x)
        (&d_g[0][0])[j] = 0.0f;
}

// ---------------------------------------------------------------------------
__device__ __forceinline__ void load_batch_q(short4* d16, char4* d8,
                                             const short4* __restrict__ Q16v,
                                             const char4*  __restrict__ Q8v,
                                             size_t qb) {
    #pragma unroll
    for (int i = 0; i < 8; ++i) {
        d16[i] = Q16v[qb + (size_t)i * (MDIM / 4)];
        d8[i]  = Q8v [qb + (size_t)i * (MDIM / 4)];
    }
}

// decode q16+q8 -> qf, then same row/col accumulation as fp32 version.
// xsI_s[r] = s1[I+r] * x[I+r] (scaled, for col mirror). Row scale applied later.
__device__ __forceinline__ void compute_batch_q(const short4* q16, const char4* q8,
                                                int roff, bool diagk,
                                                int w, int lane,
                                                const float* xsI_s,
                                                float4 xj, float* rp, float4& ca) {
    if (!diagk) {
        #pragma unroll
        for (int i = 0; i < 8; ++i) {
            float4 qf;
            qf.x = fmaf((float)q8[i].x, INV254, (float)q16[i].x);
            qf.y = fmaf((float)q8[i].y, INV254, (float)q16[i].y);
            qf.z = fmaf((float)q8[i].z, INV254, (float)q16[i].z);
            qf.w = fmaf((float)q8[i].w, INV254, (float)q16[i].w);
            float xis = xsI_s[w * 16 + roff + i];
            rp[roff + i] += qf.x * xj.x + qf.y * xj.y + qf.z * xj.z + qf.w * xj.w;
            ca.x = fmaf(qf.x, xis, ca.x);
            ca.y = fmaf(qf.y, xis, ca.y);
            ca.z = fmaf(qf.z, xis, ca.z);
            ca.w = fmaf(qf.w, xis, ca.w);
        }
    } else {
        int c0 = 4 * lane;
        #pragma unroll
        for (int i = 0; i < 8; ++i) {
            float4 qf;
            qf.x = fmaf((float)q8[i].x, INV254, (float)q16[i].x);
            qf.y = fmaf((float)q8[i].y, INV254, (float)q16[i].y);
            qf.z = fmaf((float)q8[i].z, INV254, (float)q16[i].z);
            qf.w = fmaf((float)q8[i].w, INV254, (float)q16[i].w);
            int r = w * 16 + roff + i;
            float xis = xsI_s[r];
            float r0 = (c0 + 0 >= r) ? qf.x * xj.x : 0.f;
            float r1 = (c0 + 1 >= r) ? qf.y * xj.y : 0.f;
            float r2 = (c0 + 2 >= r) ? qf.z * xj.z : 0.f;
            float r3 = (c0 + 3 >= r) ? qf.w * xj.w : 0.f;
            rp[roff + i] += (r0 + r1) + (r2 + r3);
            if (c0 + 0 > r) ca.x = fmaf(qf.x, xis, ca.x);
            if (c0 + 1 > r) ca.y = fmaf(qf.y, xis, ca.y);
            if (c0 + 2 > r) ca.z = fmaf(qf.z, xis, ca.z);
            if (c0 + 3 > r) ca.w = fmaf(qf.w, xis, ca.w);
        }
    }
}

// ---------------------------------------------------------------------------
// One launch per step, PDL with early trigger. Block = up to 2 tiles.
// ---------------------------------------------------------------------------
__global__ __launch_bounds__(256, 2)
void adam_symv_kernel(const float* __restrict__ mean,
                      const float* __restrict__ g_prev,
                      float* __restrict__ g_out,
                      int p, float step_lr, float inv_sqrt_bc2)
{
    __shared__ float xsI[TILE];        // raw x for band I (used as xj on diag)
    __shared__ float xsIs[TILE];       // s1-scaled x for col mirror
    __shared__ float sI1[TILE];        // row scales for band I
    __shared__ float xsJ[2][TILE];
    __shared__ float part[TILE][33];
    __shared__ float colp[2][8][TILE];

    // block -> (ti, pair-chunk)
    int b = blockIdx.x;
    int ti = 0;
    for (;;) {
        int chunks = (NT - ti + 1) >> 1;
        if (b < chunks) break;
        b -= chunks; ++ti;
    }
    int tj0 = ti + 2 * b;
    int nt  = NT - tj0; if (nt > 2) nt = 2;
    const int I = ti * TILE;
    const bool diag = (tj0 == ti);

    int tid = threadIdx.x, w = tid >> 5, lane = tid & 31;
    int q = p ^ 1;
    const short4* __restrict__ Q16v = reinterpret_cast<const short4*>(d_Q16);
    const char4*  __restrict__ Q8v  = reinterpret_cast<const char4*>(d_Q8);
    size_t rowbase = (size_t)(I + w * 16) * (MDIM / 4) + lane;

    // earliest trigger: next step may start launching (its gridsync protects it)
    cudaTriggerProgrammaticLaunchCompletion();

    // pre-sync prefetch: tile0 batches A+B (step-invariant data)
    short4 qv16[8], qn16[8];
    char4  qv8[8],  qn8[8];
    load_batch_q(qv16, qv8, Q16v, Q8v, rowbase + (size_t)tj0 * 32);
    load_batch_q(qn16, qn8, Q16v, Q8v, rowbase + (size_t)tj0 * 32 + 8 * (MDIM / 4));

    cudaGridDependencySynchronize();

    // ---- prologue: Adam step for band I + non-diag J bands; build x ----
    for (int idx = tid; idx < (1 + nt) * TILE; idx += 256) {
        int band = idx >> 7;
        int r    = idx & 127;
        int grow;
        if (band == 0) grow = I + r;
        else {
            int tj = tj0 + band - 1;
            if (tj == ti) continue;
            grow = tj * TILE + r;
        }
        float g  = g_prev[grow];
        float mt = B1f * d_MT[p][grow] + (1.0f - B1f) * g;
        float vt = B2f * d_VT[p][grow] + (1.0f - B2f) * g * g;
        float wn = d_W[p][grow] - step_lr * mt / (sqrtf(vt) * inv_sqrt_bc2 + EPSV);
        d_W[q][grow]  = wn;
        d_MT[q][grow] = mt;
        d_VT[q][grow] = vt;
        float x = wn - mean[grow];
        if (band == 0) {
            float s = d_s1[grow];
            xsI[r]  = x;
            xsIs[r] = s * x;
            sI1[r]  = s;
            if (diag) xsJ[0][r] = x;
        } else {
            xsJ[band - 1][r] = x;
        }
    }
    __syncthreads();

    // ---- main: double-buffered batches across up to 2 tiles ----
    float rp[16] = {0.f,0.f,0.f,0.f,0.f,0.f,0.f,0.f,
                    0.f,0.f,0.f,0.f,0.f,0.f,0.f,0.f};

    float4 xj0 = reinterpret_cast<const float4*>(xsJ[0])[lane];
    float4 ca0 = make_float4(0.f, 0.f, 0.f, 0.f);

    compute_batch_q(qv16, qv8, 0, diag, w, lane, xsIs, xj0, rp, ca0);   // tile0 A

    if (nt == 2) {
        load_batch_q(qv16, qv8, Q16v, Q8v, rowbase + (size_t)(tj0 + 1) * 32); // tile1 A
        compute_batch_q(qn16, qn8, 8, diag, w, lane, xsIs, xj0, rp, ca0);     // tile0 B
        reinterpret_cast<float4*>(colp[0][w])[lane] = ca0;

        float4 xj1 = reinterpret_cast<const float4*>(xsJ[1])[lane];
        float4 ca1 = make_float4(0.f, 0.f, 0.f, 0.f);
        load_batch_q(qn16, qn8, Q16v, Q8v,
                     rowbase + (size_t)(tj0 + 1) * 32 + 8 * (MDIM / 4));      // tile1 B
        compute_batch_q(qv16, qv8, 0, false, w, lane, xsIs, xj1, rp, ca1);    // tile1 A
        compute_batch_q(qn16, qn8, 8, false, w, lane, xsIs, xj1, rp, ca1);    // tile1 B
        reinterpret_cast<float4*>(colp[1][w])[lane] = ca1;
    } else {
        compute_batch_q(qn16, qn8, 8, diag, w, lane, xsIs, xj0, rp, ca0);     // tile0 B
        reinterpret_cast<float4*>(colp[0][w])[lane] = ca0;
    }

    // ---- row partial dump + reduce (apply row scale) + flush ----
    #pragma unroll
    for (int k = 0; k < 16; ++k)
        part[w * 16 + k][lane] = rp[k];
    __syncthreads();

    if (tid < TILE) {
        float acc = 0.f;
        #pragma unroll
        for (int l = 0; l < 32; ++l) acc += part[tid][l];
        atomicAdd(&g_out[I + tid], acc * sI1[tid]);
        if (nt == 2) {
            float acc1 = 0.f;
            #pragma unroll
            for (int ww = 0; ww < 8; ++ww) acc1 += colp[1][ww][tid];
            atomicAdd(&g_out[(tj0 + 1) * TILE + tid], acc1);
        }
    } else {
        int c = tid - TILE;
        float acc0 = 0.f;
        #pragma unroll
        for (int ww = 0; ww < 8; ++ww) acc0 += colp[0][ww][c];
        atomicAdd(&g_out[tj0 * TILE + c], acc0);
    }
}

// ---------------------------------------------------------------------------
__global__ void finish_kernel(float* __restrict__ out,
                              const float* __restrict__ g_last,
                              int p, float step_lr, float inv_sqrt_bc2) {
    cudaGridDependencySynchronize();
    int i = blockIdx.x * blockDim.x + threadIdx.x;
    if (i < MDIM) {
        float g  = g_last[i];
        float mt = B1f * d_MT[p][i] + (1.0f - B1f) * g;
        float vt = B2f * d_VT[p][i] + (1.0f - B2f) * g * g;
        out[i] = d_W[p][i] - step_lr * mt / (sqrtf(vt) * inv_sqrt_bc2 + EPSV);
    }
}

// ---------------------------------------------------------------------------
extern "C" void kernel_launch(void* const* d_in, const int* in_sizes, int n_in,
                              void* d_out, int out_size) {
    const float* mean = (const float*)d_in[0];
    const float* va   = (const float*)d_in[1];
    float* out = (float*)d_out;
    (void)in_sizes; (void)n_in; (void)out_size;

    float* g_base; cudaGetSymbolAddress((void**)&g_base, d_g);

    dim3 tb(32, 32), tg(MDIM / 32, MDIM / 32);
    prep_qs_kernel<<<tg, tb>>>(va);
    rowscale_kernel<<<MDIM, 128>>>();
    quant_kernel<<<dim3(NT, NT), 256>>>();
    init_kernel<<<128, 256>>>();

    cudaLaunchAttribute attrs[1];
    attrs[0].id = cudaLaunchAttributeProgrammaticStreamSerialization;
    attrs[0].val.programmaticStreamSerializationAllowed = 1;

    for (int s = 1; s <= NSTEPS; ++s) {
        int t = s - 1;
        float step_lr = 0.f, inv_b2 = 0.f;
        if (t >= 1) {
            double bc1 = 1.0 - pow(0.9,   (double)t);
            double bc2 = 1.0 - pow(0.999, (double)t);
            step_lr = (float)((double)LRV / bc1);
            inv_b2  = (float)(1.0 / sqrt(bc2));
        }
        int p = (s - 1) & 1;

        cudaLaunchConfig_t cfg = {};
        cfg.gridDim  = dim3(NCHUNK, 1, 1);
        cfg.blockDim = dim3(256, 1, 1);
        cfg.attrs    = attrs;
        cfg.numAttrs = 1;
        cudaLaunchKernelEx(&cfg, adam_symv_kernel, mean,
                           (const float*)(g_base + (size_t)(s - 1) * MDIM),
                           (float*)(g_base + (size_t)s * MDIM),
                           p, step_lr, inv_b2);
    }

    {
        int t = NSTEPS;
        double bc1 = 1.0 - pow(0.9,   (double)t);
        double bc2 = 1.0 - pow(0.999, (double)t);
        float step_lr = (float)((double)LRV / bc1);
        float inv_b2  = (float)(1.0 / sqrt(bc2));

        cudaLaunchConfig_t cfg = {};
        cfg.gridDim  = dim3((MDIM + 255) / 256, 1, 1);
        cfg.blockDim = dim3(256, 1, 1);
        cfg.attrs    = attrs;
        cfg.numAttrs = 1;
        cudaLaunchKernelEx(&cfg, finish_kernel, out,
                           (const float*)(g_base + (size_t)NSTEPS * MDIM),
                           (int)(NSTEPS & 1), step_lr, inv_b2);
    }
}

// round 14
// speedup vs baseline: 1.8538x; 1.8538x over previous
#include <cuda_runtime.h>
#include <math.h>

#define MDIM 4096
#define NT 32             // 32 tile-rows of 128
#define TILE 128
#define NCHUNK 272        // sum over ti of ceil((32-ti)/2)
#define B1f 0.9f
#define B2f 0.999f
#define EPSV 1e-8f
#define LRV 0.1f
#define NSTEPS 199

// ---- scratch (__device__ globals; no allocation) ----
__device__ float d_Qs[(size_t)MDIM * MDIM];      // symmetrized fp32 (upper half valid)
__device__ float d_g[(NSTEPS + 1)][MDIM];
__device__ float d_W[2][MDIM];
__device__ float d_MT[2][MDIM];
__device__ float d_VT[2][MDIM];

// ---------------------------------------------------------------------------
__global__ void prep_qs_kernel(const float* __restrict__ va) {
    __shared__ float tile[32][33];
    int bx = blockIdx.x * 32, by = blockIdx.y * 32;
    if (bx + 32 <= by) return;                   // upper-triangle blocks only
    int tx = threadIdx.x, ty = threadIdx.y;
    tile[ty][tx] = va[(size_t)(bx + ty) * MDIM + (by + tx)];
    __syncthreads();
    size_t idx = (size_t)(by + ty) * MDIM + (bx + tx);
    d_Qs[idx] = 0.5f * (va[idx] + tile[tx][ty]);
}

// ---------------------------------------------------------------------------
__global__ void init_kernel() {
    int i = blockIdx.x * blockDim.x + threadIdx.x;
    if (i < MDIM) {
        d_W[0][i] = 1.0f;  d_W[1][i] = 1.0f;
        d_MT[0][i] = 0.0f; d_MT[1][i] = 0.0f;
        d_VT[0][i] = 0.0f; d_VT[1][i] = 0.0f;
    }
    int total = (NSTEPS + 1) * MDIM;
    for (int j = i; j < total; j += gridDim.x * blockDim.x)
        (&d_g[0][0])[j] = 0.0f;
}

// ---------------------------------------------------------------------------
__device__ __forceinline__ void load_batch(float4* dst, const float4* __restrict__ Q4,
                                           size_t qb) {
    #pragma unroll
    for (int i = 0; i < 8; ++i)
        dst[i] = Q4[qb + (size_t)i * (MDIM / 4)];
}

__device__ __forceinline__ void compute_batch(const float4* qv, int roff, bool diagk,
                                              int w, int lane, const float* xsI,
                                              float4 xj, float* rp, float4& ca) {
    if (!diagk) {
        #pragma unroll
        for (int i = 0; i < 8; ++i) {
            float xi = xsI[w * 16 + roff + i];
            rp[roff + i] += qv[i].x * xj.x + qv[i].y * xj.y
                          + qv[i].z * xj.z + qv[i].w * xj.w;
            ca.x = fmaf(qv[i].x, xi, ca.x);
            ca.y = fmaf(qv[i].y, xi, ca.y);
            ca.z = fmaf(qv[i].z, xi, ca.z);
            ca.w = fmaf(qv[i].w, xi, ca.w);
        }
    } else {
        int c0 = 4 * lane;
        #pragma unroll
        for (int i = 0; i < 8; ++i) {
            int r = w * 16 + roff + i;
            float xi = xsI[r];
            float r0 = (c0 + 0 >= r) ? qv[i].x * xj.x : 0.f;
            float r1 = (c0 + 1 >= r) ? qv[i].y * xj.y : 0.f;
            float r2 = (c0 + 2 >= r) ? qv[i].z * xj.z : 0.f;
            float r3 = (c0 + 3 >= r) ? qv[i].w * xj.w : 0.f;
            rp[roff + i] += (r0 + r1) + (r2 + r3);
            if (c0 + 0 > r) ca.x = fmaf(qv[i].x, xi, ca.x);
            if (c0 + 1 > r) ca.y = fmaf(qv[i].y, xi, ca.y);
            if (c0 + 2 > r) ca.z = fmaf(qv[i].z, xi, ca.z);
            if (c0 + 3 > r) ca.w = fmaf(qv[i].w, xi, ca.w);
        }
    }
}

// ---------------------------------------------------------------------------
// One launch per step, PDL-overlapped with EARLY trigger. Block = up to 2
// tiles in one tile-row. Pre-sync preamble touches ONLY step-invariant d_Qs.
// ---------------------------------------------------------------------------
__global__ __launch_bounds__(256, 2)
void adam_symv_kernel(const float* __restrict__ mean,
                      const float* __restrict__ g_prev,
                      float* __restrict__ g_out,
                      int p, float step_lr, float inv_sqrt_bc2)
{
    __shared__ float xsI[TILE];
    __shared__ float xsJ[2][TILE];
    __shared__ float part[TILE][33];
    __shared__ float colp[2][8][TILE];

    // block -> (ti, pair-chunk)
    int b = blockIdx.x;
    int ti = 0;
    for (;;) {
        int chunks = (NT - ti + 1) >> 1;
        if (b < chunks) break;
        b -= chunks; ++ti;
    }
    int tj0 = ti + 2 * b;
    int nt  = NT - tj0; if (nt > 2) nt = 2;
    const int I = ti * TILE;
    const bool diag = (tj0 == ti);     // only tile0 can be diagonal

    int tid = threadIdx.x, w = tid >> 5, lane = tid & 31;
    int q = p ^ 1;
    const float4* __restrict__ Q4 = reinterpret_cast<const float4*>(d_Qs);
    size_t rowbase = (size_t)(I + w * 16) * (MDIM / 4) + lane;

    // earliest trigger: let the NEXT step's grid start launching now.
    cudaTriggerProgrammaticLaunchCompletion();

    // pre-sync preamble: prefetch tile0 batches A+B (step-invariant data)
    float4 qv[8], qn[8];
    load_batch(qv, Q4, rowbase + (size_t)tj0 * 32);
    load_batch(qn, Q4, rowbase + (size_t)tj0 * 32 + 8 * (MDIM / 4));

    // wait for upstream step's memory to be visible (no-op if PDL inactive)
    cudaGridDependencySynchronize();

    // ---- prologue: Adam step for band I + non-diag J bands; build x ----
    for (int idx = tid; idx < (1 + nt) * TILE; idx += 256) {
        int band = idx >> 7;
        int r    = idx & 127;
        int grow;
        if (band == 0) grow = I + r;
        else {
            int tj = tj0 + band - 1;
            if (tj == ti) continue;
            grow = tj * TILE + r;
        }
        float g  = g_prev[grow];
        float mt = B1f * d_MT[p][grow] + (1.0f - B1f) * g;
        float vt = B2f * d_VT[p][grow] + (1.0f - B2f) * g * g;
        float wn = d_W[p][grow]
                 - __fdividef(step_lr * mt, sqrtf(vt) * inv_sqrt_bc2 + EPSV);
        d_W[q][grow]  = wn;
        d_MT[q][grow] = mt;
        d_VT[q][grow] = vt;
        float x = wn - mean[grow];
        if (band == 0) {
            xsI[r] = x;
            if (diag) xsJ[0][r] = x;
        } else {
            xsJ[band - 1][r] = x;
        }
    }
    __syncthreads();

    // ---- main: double-buffered 8-row batches across up to 2 tiles ----
    float rp[16] = {0.f,0.f,0.f,0.f,0.f,0.f,0.f,0.f,
                    0.f,0.f,0.f,0.f,0.f,0.f,0.f,0.f};

    float4 xj0 = reinterpret_cast<const float4*>(xsJ[0])[lane];
    float4 ca0 = make_float4(0.f, 0.f, 0.f, 0.f);

    compute_batch(qv, 0, diag, w, lane, xsI, xj0, rp, ca0);             // tile0 A

    if (nt == 2) {
        load_batch(qv, Q4, rowbase + (size_t)(tj0 + 1) * 32);           // tile1 A
        compute_batch(qn, 8, diag, w, lane, xsI, xj0, rp, ca0);         // tile0 B
        reinterpret_cast<float4*>(colp[0][w])[lane] = ca0;

        float4 xj1 = reinterpret_cast<const float4*>(xsJ[1])[lane];
        float4 ca1 = make_float4(0.f, 0.f, 0.f, 0.f);
        load_batch(qn, Q4, rowbase + (size_t)(tj0 + 1) * 32 + 8 * (MDIM / 4)); // tile1 B
        compute_batch(qv, 0, false, w, lane, xsI, xj1, rp, ca1);        // tile1 A
        compute_batch(qn, 8, false, w, lane, xsI, xj1, rp, ca1);        // tile1 B
        reinterpret_cast<float4*>(colp[1][w])[lane] = ca1;
    } else {
        compute_batch(qn, 8, diag, w, lane, xsI, xj0, rp, ca0);         // tile0 B
        reinterpret_cast<float4*>(colp[0][w])[lane] = ca0;
    }

    // ---- row partial dump + balanced reduce + flush ----
    #pragma unroll
    for (int k = 0; k < 16; ++k)
        part[w * 16 + k][lane] = rp[k];
    __syncthreads();

    if (tid < TILE) {
        // rows only (32 adds)
        float acc = 0.f;
        #pragma unroll
        for (int l = 0; l < 32; ++l) acc += part[tid][l];
        atomicAdd(&g_out[I + tid], acc);
    } else {
        // both column flushes (8 + 8 adds)
        int c = tid - TILE;
        float acc0 = 0.f;
        #pragma unroll
        for (int ww = 0; ww < 8; ++ww) acc0 += colp[0][ww][c];
        atomicAdd(&g_out[tj0 * TILE + c], acc0);
        if (nt == 2) {
            float acc1 = 0.f;
            #pragma unroll
            for (int ww = 0; ww < 8; ++ww) acc1 += colp[1][ww][c];
            atomicAdd(&g_out[(tj0 + 1) * TILE + c], acc1);
        }
    }
}

// ---------------------------------------------------------------------------
__global__ void finish_kernel(float* __restrict__ out,
                              const float* __restrict__ g_last,
                              int p, float step_lr, float inv_sqrt_bc2) {
    cudaGridDependencySynchronize();
    int i = blockIdx.x * blockDim.x + threadIdx.x;
    if (i < MDIM) {
        float g  = g_last[i];
        float mt = B1f * d_MT[p][i] + (1.0f - B1f) * g;
        float vt = B2f * d_VT[p][i] + (1.0f - B2f) * g * g;
        out[i] = d_W[p][i] - step_lr * mt / (sqrtf(vt) * inv_sqrt_bc2 + EPSV);
    }
}

// ---------------------------------------------------------------------------
extern "C" void kernel_launch(void* const* d_in, const int* in_sizes, int n_in,
                              void* d_out, int out_size) {
    const float* mean = (const float*)d_in[0];
    const float* va   = (const float*)d_in[1];
    float* out = (float*)d_out;
    (void)in_sizes; (void)n_in; (void)out_size;

    float* g_base; cudaGetSymbolAddress((void**)&g_base, d_g);

    dim3 tb(32, 32), tg(MDIM / 32, MDIM / 32);
    prep_qs_kernel<<<tg, tb>>>(va);
    init_kernel<<<128, 256>>>();

    cudaLaunchAttribute attrs[1];
    attrs[0].id = cudaLaunchAttributeProgrammaticStreamSerialization;
    attrs[0].val.programmaticStreamSerializationAllowed = 1;

    for (int s = 1; s <= NSTEPS; ++s) {
        int t = s - 1;
        float step_lr = 0.f, inv_b2 = 0.f;
        if (t >= 1) {
            double bc1 = 1.0 - pow(0.9,   (double)t);
            double bc2 = 1.0 - pow(0.999, (double)t);
            step_lr = (float)((double)LRV / bc1);
            inv_b2  = (float)(1.0 / sqrt(bc2));
        }
        int p = (s - 1) & 1;

        cudaLaunchConfig_t cfg = {};
        cfg.gridDim  = dim3(NCHUNK, 1, 1);
        cfg.blockDim = dim3(256, 1, 1);
        cfg.attrs    = attrs;
        cfg.numAttrs = 1;
        cudaLaunchKernelEx(&cfg, adam_symv_kernel, mean,
                           (const float*)(g_base + (size_t)(s - 1) * MDIM),
                           (float*)(g_base + (size_t)s * MDIM),
                           p, step_lr, inv_b2);
    }

    {
        int t = NSTEPS;
        double bc1 = 1.0 - pow(0.9,   (double)t);
        double bc2 = 1.0 - pow(0.999, (double)t);
        float step_lr = (float)((double)LRV / bc1);
        float inv_b2  = (float)(1.0 / sqrt(bc2));

        cudaLaunchConfig_t cfg = {};
        cfg.gridDim  = dim3((MDIM + 255) / 256, 1, 1);
        cfg.blockDim = dim3(256, 1, 1);
        cfg.attrs    = attrs;
        cfg.numAttrs = 1;
        cudaLaunchKernelEx(&cfg, finish_kernel, out,
                           (const float*)(g_base + (size_t)NSTEPS * MDIM),
                           (int)(NSTEPS & 1), step_lr, inv_b2);
    }
}